// round 5
// baseline (speedup 1.0000x reference)
#include <cuda_runtime.h>
#include <cuda_bf16.h>
#include <math.h>
#include <stdint.h>

#define BB 8
#define HH 1024
#define DD 4
#define TI 16          // output rows per block
#define TJ 128         // j-tile width
#define NTILE (HH / TJ)
#define PADJ 132       // shAT row stride in floats (conflict-free column reads)
#define NBUF 2

// Scratch (__device__ globals: allocation-guard safe)
__device__ uint32_t g_casa[HH * HH];   // packed bf16x2: lo = 0.5*cos(alpha), hi = 0.5*sin(alpha)
__device__ float    g_sth[BB * HH * DD];
__device__ float    g_cth[BB * HH * DD];

typedef unsigned long long u64;

__device__ __forceinline__ u64 pack2(float x, float y) {
    u64 r; asm("mov.b64 %0, {%1, %2};" : "=l"(r) : "f"(x), "f"(y)); return r;
}
__device__ __forceinline__ u64 ffma2(u64 a, u64 b, u64 c) {
    u64 d; asm("fma.rn.f32x2 %0, %1, %2, %3;" : "=l"(d) : "l"(a), "l"(b), "l"(c)); return d;
}
__device__ __forceinline__ float2 unpk2(u64 v) {
    float x, y; asm("mov.b64 {%0, %1}, %2;" : "=f"(x), "=f"(y) : "l"(v));
    return make_float2(x, y);
}
__device__ __forceinline__ void cp_async4(uint32_t s, const void* g) {
    asm volatile("cp.async.ca.shared.global [%0], [%1], 4;" :: "r"(s), "l"(g));
}
__device__ __forceinline__ void cp_async16(uint32_t s, const void* g) {
    asm volatile("cp.async.cg.shared.global [%0], [%1], 16;" :: "r"(s), "l"(g));
}
__device__ __forceinline__ void cp_commit() { asm volatile("cp.async.commit_group;"); }
__device__ __forceinline__ void cp_wait1()  { asm volatile("cp.async.wait_group 1;"); }

// ---------------------------------------------------------------------------
// Kernel 1: trig precompute. casa packed to bf16x2 (0.5 factor folded in).
// ---------------------------------------------------------------------------
__global__ void vk_trig_kernel(const float* __restrict__ alpha,
                               const float* __restrict__ theta) {
    int idx = blockIdx.x * blockDim.x + threadIdx.x;
    const int NA = HH * HH;
    const int NT = BB * HH * DD;
    if (idx < NA) {
        float s, c;
        sincosf(alpha[idx], &s, &c);
        uint32_t cb = (uint32_t)__bfloat16_as_ushort(__float2bfloat16(0.5f * c));
        uint32_t sb = (uint32_t)__bfloat16_as_ushort(__float2bfloat16(0.5f * s));
        g_casa[idx] = (sb << 16) | cb;
    } else if (idx < NA + NT) {
        int t = idx - NA;
        float s, c;
        sincosf(theta[t], &s, &c);
        g_sth[t] = s;
        g_cth[t] = c;
    }
}

// One (i,j) pair: m = relu(ar+at); w1 = m*ca'; w2 = m*sa'
// s1 += w1*s - w2*c ; s2 += w1*c + w2*s   (packed f32x2 over d-pairs)
#define KPAIR(ar, at, caf, saf, Sv, Cv, P0, P1, P2, P3)      \
    {                                                        \
        float m_  = fmaxf((ar) + (at), 0.f);                 \
        float w1_ = m_ * (caf);                              \
        float w2_ = m_ * (saf);                              \
        float n2_ = -w2_;                                    \
        u64 w1p_ = pack2(w1_, w1_);                          \
        u64 w2p_ = pack2(w2_, w2_);                          \
        u64 n2p_ = pack2(n2_, n2_);                          \
        P0 = ffma2(w1p_, (Sv).x, P0); P0 = ffma2(n2p_, (Cv).x, P0); \
        P1 = ffma2(w1p_, (Sv).y, P1); P1 = ffma2(n2p_, (Cv).y, P1); \
        P2 = ffma2(w1p_, (Cv).x, P2); P2 = ffma2(w2p_, (Sv).x, P2); \
        P3 = ffma2(w1p_, (Cv).y, P3); P3 = ffma2(w2p_, (Sv).y, P3); \
    }

// ---------------------------------------------------------------------------
// Kernel 2: main coupling. Grid (H/TI, B), block 256 = 8 warps, 2 rows/warp.
// 2-stage cp.async pipeline stages A^T tile, A-row tile, and theta-trig tile.
// Inner loop: SMEM loads + one bf16x2 LDG (L2-resident 4MB casa table).
// ---------------------------------------------------------------------------
__global__ __launch_bounds__(256, 4)
void vk_main_kernel(const float* __restrict__ theta,
                    const float* __restrict__ gamma,
                    const float* __restrict__ A,
                    const float* __restrict__ omega,
                    const float* __restrict__ kappa,
                    float* __restrict__ out) {
    __shared__ float      shAT[NBUF][TI * PADJ]; // [ii][jj] = A[b, j0+jj, i0+ii]
    __shared__ float      shAR[NBUF][TI * TJ];   // [ii][jj] = A[b, i0+ii, j0+jj]
    __shared__ ulonglong2 shS[NBUF][TJ];         // sin(theta[b, j0+jj, 0..3])
    __shared__ ulonglong2 shC[NBUF][TJ];         // cos(theta[b, j0+jj, 0..3])

    const int b    = blockIdx.y;
    const int i0   = blockIdx.x * TI;
    const int tid  = threadIdx.x;
    const int warp = tid >> 5;
    const int lane = tid & 31;

    const float* Ab   = A + (size_t)b * HH * HH;
    const float* sthb = g_sth + (size_t)b * HH * DD;
    const float* cthb = g_cth + (size_t)b * HH * DD;

    const int riA = warp * 2;
    const int iA  = i0 + riA;
    const uint32_t* csAp = g_casa + (size_t)iA * HH;   // packed bf16 (ca,sa), row A
    const uint32_t* csBp = csAp + HH;                  // row B

    const int s_ii = tid & 15;   // A^T staging: fast gmem index
    const int s_jj = tid >> 4;

    auto stage = [&](int tt, int sb) {
        const int j0_ = tt * TJ;
        // A^T tile: 8x cp.async4 (gmem coalesced over ii, smem [ii][jj])
        uint32_t dAT = (uint32_t)__cvta_generic_to_shared(&shAT[sb][0]);
        #pragma unroll
        for (int p = 0; p < 8; p++) {
            int jj = s_jj + p * 16;
            cp_async4(dAT + (uint32_t)(s_ii * PADJ + jj) * 4,
                      Ab + (size_t)(j0_ + jj) * HH + (i0 + s_ii));
        }
        // A-row tile: 512 float4 -> 2x cp.async16 per thread
        uint32_t dAR = (uint32_t)__cvta_generic_to_shared(&shAR[sb][0]);
        #pragma unroll
        for (int p = 0; p < 2; p++) {
            int f  = tid + 256 * p;          // float4 index
            int ii = f >> 5;                 // 32 float4 per row
            int jq = f & 31;
            cp_async16(dAR + (uint32_t)f * 16,
                       Ab + (size_t)(i0 + ii) * HH + j0_ + jq * 4);
        }
        // theta trig: 1x cp.async16 per thread
        if (tid < 128) {
            cp_async16((uint32_t)__cvta_generic_to_shared(&shS[sb][tid]),
                       sthb + (size_t)(j0_ + tid) * DD);
        } else {
            cp_async16((uint32_t)__cvta_generic_to_shared(&shC[sb][tid - 128]),
                       cthb + (size_t)(j0_ + tid - 128) * DD);
        }
    };

    u64 A0 = 0, A1 = 0, A2 = 0, A3 = 0;  // row A: s1 d01, s1 d23, s2 d01, s2 d23
    u64 B0 = 0, B1 = 0, B2 = 0, B3 = 0;  // row B

    stage(0, 0); cp_commit();

    int sb = 0;
    for (int t = 0; t < NTILE; t++) {
        __syncthreads();                       // all warps done with tile t-1 (buffer sb^1 free)
        if (t + 1 < NTILE) stage(t + 1, sb ^ 1);
        cp_commit();                           // exactly one group per iter
        cp_wait1();                            // group t complete (t+1 may be in flight)
        __syncthreads();

        const float*      bAT  = shAT[sb];
        const float*      bAR  = shAR[sb];
        const ulonglong2* bufS = shS[sb];
        const ulonglong2* bufC = shC[sb];
        const int j0 = t * TJ;

        #pragma unroll
        for (int q = 0; q < 4; q++) {
            const int jl = q * 32 + lane;
            const int j  = j0 + jl;
            ulonglong2 Sv = bufS[jl];                    // LDS.128, conflict-free
            ulonglong2 Cv = bufC[jl];
            float atA = bAT[riA * PADJ + jl];            // LDS.32, lane-consecutive
            float atB = bAT[(riA + 1) * PADJ + jl];
            float arA = bAR[riA * TJ + jl];
            float arB = bAR[(riA + 1) * TJ + jl];
            uint32_t csA = csAp[j];                      // LDG.32 (L2-resident table)
            uint32_t csB = csBp[j];
            float caA = __uint_as_float(csA << 16);
            float saA = __uint_as_float(csA & 0xFFFF0000u);
            float caB = __uint_as_float(csB << 16);
            float saB = __uint_as_float(csB & 0xFFFF0000u);
            KPAIR(arA, atA, caA, saA, Sv, Cv, A0, A1, A2, A3);
            KPAIR(arB, atB, caB, saB, Sv, Cv, B0, B1, B2, B3);
        }
        sb ^= 1;
    }

    // Unpack + warp butterfly reduction (16 scalars)
    float v[16];
    {
        float2 t2;
        t2 = unpk2(A0); v[0]  = t2.x; v[1]  = t2.y;
        t2 = unpk2(A1); v[2]  = t2.x; v[3]  = t2.y;
        t2 = unpk2(A2); v[4]  = t2.x; v[5]  = t2.y;
        t2 = unpk2(A3); v[6]  = t2.x; v[7]  = t2.y;
        t2 = unpk2(B0); v[8]  = t2.x; v[9]  = t2.y;
        t2 = unpk2(B1); v[10] = t2.x; v[11] = t2.y;
        t2 = unpk2(B2); v[12] = t2.x; v[13] = t2.y;
        t2 = unpk2(B3); v[14] = t2.x; v[15] = t2.y;
    }
    #pragma unroll
    for (int off = 16; off > 0; off >>= 1) {
        #pragma unroll
        for (int qq = 0; qq < 16; qq++)
            v[qq] += __shfl_xor_sync(0xFFFFFFFFu, v[qq], off);
    }

    if (lane < 2) {
        const int i = iA + lane;
        const float* vv = v + lane * 8;       // [s1_d0..d3, s2_d0..d3]
        const float invH = 1.0f / (float)HH;  // K_COUP=1, DT=1, 0.5 folded
        const size_t base = ((size_t)b * HH + i) * DD;
        float4 si4 = *(const float4*)(g_sth + base);
        float4 ci4 = *(const float4*)(g_cth + base);
        float4 tp4 = *(const float4*)(theta + base);
        float4 om4 = *(const float4*)(omega + (size_t)i * DD);
        float4 kp4 = *(const float4*)(kappa + (size_t)i * DD);
        float g = gamma[(size_t)b * HH + i];

        float4 rr;
        rr.x = tp4.x + om4.x + invH * (ci4.x * vv[0] - si4.x * vv[4]) + kp4.x * (g - tp4.x);
        rr.y = tp4.y + om4.y + invH * (ci4.y * vv[1] - si4.y * vv[5]) + kp4.y * (g - tp4.y);
        rr.z = tp4.z + om4.z + invH * (ci4.z * vv[2] - si4.z * vv[6]) + kp4.z * (g - tp4.z);
        rr.w = tp4.w + om4.w + invH * (ci4.w * vv[3] - si4.w * vv[7]) + kp4.w * (g - tp4.w);
        *(float4*)(out + base) = rr;
    }
}

extern "C" void kernel_launch(void* const* d_in, const int* in_sizes, int n_in,
                              void* d_out, int out_size) {
    const float* theta = (const float*)d_in[0];  // [B,H,D]
    const float* gamma = (const float*)d_in[1];  // [B,H]
    const float* A     = (const float*)d_in[2];  // [B,H,H]
    const float* omega = (const float*)d_in[3];  // [H,D]
    const float* kappa = (const float*)d_in[4];  // [H,D]
    const float* alpha = (const float*)d_in[5];  // [H,H]
    float* out = (float*)d_out;

    {
        int n = HH * HH + BB * HH * DD;
        int threads = 256;
        int blocks = (n + threads - 1) / threads;
        vk_trig_kernel<<<blocks, threads>>>(alpha, theta);
    }
    {
        dim3 grid(HH / TI, BB);
        vk_main_kernel<<<grid, 256>>>(theta, gamma, A, omega, kappa, out);
    }
}